// round 3
// baseline (speedup 1.0000x reference)
#include <cuda_runtime.h>
#include <math.h>

#define N_ATOMS 4096
#define NG      128
#define QKV_LD  768

// Scratch (no allocations allowed)
__device__ float g_qkv[N_ATOMS * QKV_LD];   // per row: [0:256)=Q [256:512)=K [512:768)=V
__device__ float g_segsum[NG * 256];        // per-group summed attention output
__device__ float g_wct[256 * 256];          // Wct[f][j] = (Wo2 @ Wo1)^T
__device__ float g_bc[256];                 // bc = Wo2 @ bo1

__device__ __forceinline__ float to_tf32(float x) {
    asm("cvt.rna.tf32.f32 %0, %0;" : "+f"(x));
    return x;
}

__device__ __forceinline__ void mma_tf32(float c[4], const unsigned a[4], const unsigned b[2]) {
    asm volatile(
        "mma.sync.aligned.m16n8k8.row.col.f32.tf32.tf32.f32 "
        "{%0,%1,%2,%3}, {%4,%5,%6,%7}, {%8,%9}, {%0,%1,%2,%3};"
        : "+f"(c[0]), "+f"(c[1]), "+f"(c[2]), "+f"(c[3])
        : "r"(a[0]), "r"(a[1]), "r"(a[2]), "r"(a[3]), "r"(b[0]), "r"(b[1]));
}

__device__ __forceinline__ float silu(float v) {
    return __fdividef(v, 1.0f + __expf(-v));
}

// ---------------------------------------------------------------------------
// k1 mega-kernel:
//   blocks [0,384)   : TF32 QKV projection  C[4096x768] = x @ [Wq|Wk|Wv]^T + b
//   blocks [384,416) : fp32 Wct[f][j] = sum_k Wo1[k][f] * Wo2[j][k]
//   blocks [416,424) : fp32 bc[j]     = sum_k Wo2[j][k] * bo1[k]
// All three are independent; the small weight-combine work hides inside the
// projection's ~2.6 waves.
// ---------------------------------------------------------------------------
#define PROJ_BLOCKS 384
#define WC_BLOCKS   32
#define K1_BLOCKS   (PROJ_BLOCKS + WC_BLOCKS + 8)

__global__ __launch_bounds__(256) void k1(
        const float* __restrict__ x,
        const float* __restrict__ Wq, const float* __restrict__ bq,
        const float* __restrict__ Wk, const float* __restrict__ bk,
        const float* __restrict__ Wv, const float* __restrict__ bv,
        const float* __restrict__ Wo1, const float* __restrict__ bo1,
        const float* __restrict__ Wo2)
{
    __shared__ float sh[6912];      // proj: As 128x36 + Bs 64x36 ; wc: 32x36 + 32x68
    const int bid = blockIdx.x;
    const int tid = threadIdx.x;

    if (bid < PROJ_BLOCKS) {
        // ---------------- TF32 projection ----------------
        float (*As)[36] = (float(*)[36])sh;            // [128][36]
        float (*Bs)[36] = (float(*)[36])(sh + 4608);   // [64][36]

        const int warp = tid >> 5;
        const int lane = tid & 31;
        const int grp  = lane >> 2;
        const int tig  = lane & 3;
        const int wm   = warp >> 1;
        const int wn   = warp & 1;

        const int n0 = (bid / 12) * 128;
        const int j0 = (bid % 12) * 64;
        const int sel = j0 >> 8;
        const float* __restrict__ W = (sel == 0) ? Wq : (sel == 1 ? Wk : Wv);
        const float* __restrict__ b = (sel == 0) ? bq : (sel == 1 ? bk : bv);
        const int jl = j0 & 255;

        float c[2][4][4] = {};

        for (int k0 = 0; k0 < 256; k0 += 32) {
            #pragma unroll
            for (int it = 0; it < 4; it++) {
                int idx = tid + it * 256;
                int row = idx >> 3;
                int c4  = idx & 7;
                float4 a = *(const float4*)&x[(n0 + row) * 256 + k0 + c4 * 4];
                a.x = to_tf32(a.x); a.y = to_tf32(a.y); a.z = to_tf32(a.z); a.w = to_tf32(a.w);
                *(float4*)&As[row][c4 * 4] = a;
            }
            #pragma unroll
            for (int it = 0; it < 2; it++) {
                int idx = tid + it * 256;
                int row = idx >> 3;
                int c4  = idx & 7;
                float4 w = *(const float4*)&W[(jl + row) * 256 + k0 + c4 * 4];
                w.x = to_tf32(w.x); w.y = to_tf32(w.y); w.z = to_tf32(w.z); w.w = to_tf32(w.w);
                *(float4*)&Bs[row][c4 * 4] = w;
            }
            __syncthreads();

            #pragma unroll
            for (int ks = 0; ks < 4; ks++) {
                const int kb = ks * 8;
                unsigned af[2][4];
                #pragma unroll
                for (int mt = 0; mt < 2; mt++) {
                    int rb = wm * 32 + mt * 16;
                    af[mt][0] = __float_as_uint(As[rb + grp    ][kb + tig    ]);
                    af[mt][1] = __float_as_uint(As[rb + 8 + grp][kb + tig    ]);
                    af[mt][2] = __float_as_uint(As[rb + grp    ][kb + tig + 4]);
                    af[mt][3] = __float_as_uint(As[rb + 8 + grp][kb + tig + 4]);
                }
                unsigned bf[4][2];
                #pragma unroll
                for (int nt = 0; nt < 4; nt++) {
                    int cb = wn * 32 + nt * 8;
                    bf[nt][0] = __float_as_uint(Bs[cb + grp][kb + tig    ]);
                    bf[nt][1] = __float_as_uint(Bs[cb + grp][kb + tig + 4]);
                }
                #pragma unroll
                for (int mt = 0; mt < 2; mt++)
                    #pragma unroll
                    for (int nt = 0; nt < 4; nt++)
                        mma_tf32(c[mt][nt], af[mt], bf[nt]);
            }
            __syncthreads();
        }

        #pragma unroll
        for (int mt = 0; mt < 2; mt++) {
            int r0 = n0 + wm * 32 + mt * 16 + grp;
            int r1 = r0 + 8;
            #pragma unroll
            for (int nt = 0; nt < 4; nt++) {
                int jj  = j0 + wn * 32 + nt * 8 + tig * 2;
                int jlb = jl + wn * 32 + nt * 8 + tig * 2;
                float b0 = b[jlb], b1 = b[jlb + 1];
                *(float2*)&g_qkv[r0 * QKV_LD + jj] = make_float2(c[mt][nt][0] + b0, c[mt][nt][1] + b1);
                *(float2*)&g_qkv[r1 * QKV_LD + jj] = make_float2(c[mt][nt][2] + b0, c[mt][nt][3] + b1);
            }
        }
    } else if (bid < PROJ_BLOCKS + WC_BLOCKS) {
        // ---------------- fp32 Wct tile: 32 f-rows x 64 j-cols ----------------
        float (*As)[36] = (float(*)[36])sh;            // [32][36]: As[kk][ff] = Wo1[k0+kk][f0+ff]
        float (*Bs)[68] = (float(*)[68])(sh + 32*36);  // [32][68]: Bs[kk][jj] = Wo2[j0+jj][k0+kk]

        const int t  = bid - PROJ_BLOCKS;
        const int f0 = (t >> 2) * 32;
        const int j0 = (t & 3) * 64;
        const int ti = tid >> 4;    // 0..15 -> f = ti*2
        const int tj = tid & 15;    // 0..15 -> j = tj*4

        float acc[2][4] = {};

        for (int k0 = 0; k0 < 256; k0 += 32) {
            {
                int kk = tid >> 3;
                int fq = tid & 7;
                float4 a = *(const float4*)&Wo1[(k0 + kk) * 256 + f0 + fq * 4];
                *(float4*)&As[kk][fq * 4] = a;
            }
            #pragma unroll
            for (int it = 0; it < 2; it++) {
                int idx = tid + it * 256;
                int jj = idx >> 3;
                int kq = idx & 7;
                float4 w = *(const float4*)&Wo2[(j0 + jj) * 256 + k0 + kq * 4];
                Bs[kq * 4 + 0][jj] = w.x;
                Bs[kq * 4 + 1][jj] = w.y;
                Bs[kq * 4 + 2][jj] = w.z;
                Bs[kq * 4 + 3][jj] = w.w;
            }
            __syncthreads();
            #pragma unroll
            for (int kk = 0; kk < 32; kk++) {
                float2 a2 = *(const float2*)&As[kk][ti * 2];
                float4 b4 = *(const float4*)&Bs[kk][tj * 4];
                acc[0][0] += a2.x * b4.x; acc[0][1] += a2.x * b4.y;
                acc[0][2] += a2.x * b4.z; acc[0][3] += a2.x * b4.w;
                acc[1][0] += a2.y * b4.x; acc[1][1] += a2.y * b4.y;
                acc[1][2] += a2.y * b4.z; acc[1][3] += a2.y * b4.w;
            }
            __syncthreads();
        }
        #pragma unroll
        for (int u = 0; u < 2; u++)
            #pragma unroll
            for (int v = 0; v < 4; v++)
                g_wct[(f0 + ti * 2 + u) * 256 + j0 + tj * 4 + v] = acc[u][v];
    } else {
        // ---------------- bc[j] = Wo2[j,:] . bo1 ----------------
        const int b    = bid - PROJ_BLOCKS - WC_BLOCKS;   // 0..7
        const int w    = tid >> 5;
        const int lane = tid & 31;
        #pragma unroll
        for (int u = 0; u < 4; u++) {
            int j = b * 32 + w * 4 + u;
            float s = 0.0f;
            #pragma unroll
            for (int kc = 0; kc < 8; kc++) {
                int k = kc * 32 + lane;
                s += Wo2[j * 256 + k] * bo1[k];
            }
            #pragma unroll
            for (int off = 16; off; off >>= 1)
                s += __shfl_xor_sync(0xffffffffu, s, off);
            if (lane == 0) g_bc[j] = s;
        }
    }
}

// ---------------------------------------------------------------------------
// Attention, block-per-(group, head-half). Exploits linearity of segsum:
//   segsum_g[h,:] = sum_m ( sum_n silu(q_n.k_m) ) * v_m
// So compute per-m column sums t[m] first, then one t.V pass. No shuffles in
// the hot loop, no atomics, K/V read once per group (not once per row).
// ---------------------------------------------------------------------------
__global__ __launch_bounds__(128) void attn_kernel(const int* __restrict__ seg)
{
    __shared__ float Ks[32][132];      // pad 132 -> conflict-free LDS.128 by m-lane
    __shared__ float Vs[32][132];
    __shared__ float q_sh[2][128];
    __shared__ int sb[2];

    const int g   = blockIdx.x;
    const int hh  = blockIdx.y;        // head-half: cols [hh*128, hh*128+128)
    const int tid = threadIdx.x;
    const int w    = tid >> 5;         // local head 0..3
    const int lane = tid & 31;

    if (tid == 0) {
        int lo = 0, hi = N_ATOMS;
        while (lo < hi) { int mid = (lo + hi) >> 1; if (seg[mid] < g) lo = mid + 1; else hi = mid; }
        sb[0] = lo;
        int hi2 = N_ATOMS;
        while (lo < hi2) { int mid = (lo + hi2) >> 1; if (seg[mid] <= g) lo = mid + 1; else hi2 = mid; }
        sb[1] = lo;
    }
    __syncthreads();
    const int start = sb[0], end = sb[1];
    const int colbase = hh * 128;

    float out_acc = 0.0f;

    for (int mc = start; mc < end; mc += 32) {
        const int lc = min(32, end - mc);
        // stage K,V chunk (zero-fill tail rows so their contribution is exact 0)
        #pragma unroll
        for (int it = 0; it < 8; it++) {
            int idx = tid + it * 128;      // 0..1023
            int m   = idx >> 5;            // 0..31
            int c4  = idx & 31;            // cols c4*4
            float4 kv, vv;
            if (m < lc) {
                kv = *(const float4*)&g_qkv[(mc + m) * QKV_LD + 256 + colbase + c4 * 4];
                vv = *(const float4*)&g_qkv[(mc + m) * QKV_LD + 512 + colbase + c4 * 4];
            } else {
                kv = make_float4(0.f, 0.f, 0.f, 0.f);
                vv = kv;
            }
            *(float4*)&Ks[m][c4 * 4] = kv;
            *(float4*)&Vs[m][c4 * 4] = vv;
        }
        q_sh[0][tid] = g_qkv[start * QKV_LD + colbase + tid];
        __syncthreads();

        float t_acc = 0.0f;                // lane = m
        for (int n = start; n < end; n++) {
            int buf = (n - start) & 1;
            if (n + 1 < end)
                q_sh[buf ^ 1][tid] = g_qkv[(n + 1) * QKV_LD + colbase + tid];
            float s = 0.0f;
            #pragma unroll
            for (int d4 = 0; d4 < 8; d4++) {
                float4 q4 = *(const float4*)&q_sh[buf][w * 32 + d4 * 4];
                float4 k4 = *(const float4*)&Ks[lane][w * 32 + d4 * 4];
                s += q4.x * k4.x + q4.y * k4.y + q4.z * k4.z + q4.w * k4.w;
            }
            t_acc += silu(s);
            __syncthreads();
        }
        // AV: out[d=lane] += sum_m t[m] * V[m][d]
        #pragma unroll
        for (int m = 0; m < 32; m++) {
            float tm = __shfl_sync(0xffffffffu, t_acc, m);
            out_acc += tm * Vs[m][w * 32 + lane];
        }
        __syncthreads();   // protect Ks/Vs before next chunk staging
    }

    g_segsum[g * 256 + colbase + w * 32 + lane] = out_acc;
}

// ---------------------------------------------------------------------------
// Final: out[g][j] = silu( sum_f segsum[g][f]*Wct[f][j] + cnt_g*bc[j] + bo2[j] )
// 32 blocks x 256 threads; thread = column j, 4 g-rows per block.
// ---------------------------------------------------------------------------
__global__ __launch_bounds__(256) void final_kernel(
        const int* __restrict__ seg, const float* __restrict__ bo2,
        float* __restrict__ out)
{
    __shared__ float4 a4[256];     // a4[f] = segsum rows g0..g0+3 at column f
    __shared__ float s_cnt[4];

    const int g0  = blockIdx.x * 4;
    const int tid = threadIdx.x;

    float4 v;
    v.x = g_segsum[(g0 + 0) * 256 + tid];
    v.y = g_segsum[(g0 + 1) * 256 + tid];
    v.z = g_segsum[(g0 + 2) * 256 + tid];
    v.w = g_segsum[(g0 + 3) * 256 + tid];
    a4[tid] = v;

    if (tid < 4) {
        int g = g0 + tid;
        int lo = 0, hi = N_ATOMS;
        while (lo < hi) { int mid = (lo + hi) >> 1; if (seg[mid] < g) lo = mid + 1; else hi = mid; }
        int st = lo;
        hi = N_ATOMS;
        while (lo < hi) { int mid = (lo + hi) >> 1; if (seg[mid] <= g) lo = mid + 1; else hi = mid; }
        s_cnt[tid] = (float)(lo - st);
    }
    __syncthreads();

    float acc0 = 0.f, acc1 = 0.f, acc2 = 0.f, acc3 = 0.f;
    #pragma unroll 8
    for (int f = 0; f < 256; f++) {
        float wv = g_wct[f * 256 + tid];
        float4 a = a4[f];
        acc0 += a.x * wv;
        acc1 += a.y * wv;
        acc2 += a.z * wv;
        acc3 += a.w * wv;
    }

    float bcv = g_bc[tid];
    float b2  = bo2[tid];
    float r0 = acc0 + s_cnt[0] * bcv + b2;
    float r1 = acc1 + s_cnt[1] * bcv + b2;
    float r2 = acc2 + s_cnt[2] * bcv + b2;
    float r3 = acc3 + s_cnt[3] * bcv + b2;
    out[(g0 + 0) * 256 + tid] = silu(r0);
    out[(g0 + 1) * 256 + tid] = silu(r1);
    out[(g0 + 2) * 256 + tid] = silu(r2);
    out[(g0 + 3) * 256 + tid] = silu(r3);
}

// ---------------------------------------------------------------------------
extern "C" void kernel_launch(void* const* d_in, const int* in_sizes, int n_in,
                              void* d_out, int out_size)
{
    const float* x    = (const float*)d_in[0];
    const int*   elem = (const int*)d_in[1];
    const int*   seg  = elem + N_ATOMS;        // elem_index[1]
    const float* Wq   = (const float*)d_in[2];
    const float* bq   = (const float*)d_in[3];
    const float* Wk   = (const float*)d_in[4];
    const float* bk   = (const float*)d_in[5];
    const float* Wv   = (const float*)d_in[6];
    const float* bv   = (const float*)d_in[7];
    const float* Wo1  = (const float*)d_in[8];
    const float* bo1  = (const float*)d_in[9];
    const float* Wo2  = (const float*)d_in[10];
    const float* bo2  = (const float*)d_in[11];
    float* out = (float*)d_out;

    k1<<<K1_BLOCKS, 256>>>(x, Wq, bq, Wk, bk, Wv, bv, Wo1, bo1, Wo2);
    attn_kernel<<<dim3(NG, 2), 128>>>(seg);
    final_kernel<<<32, 256>>>(seg, bo2, out);
}

// round 4
// speedup vs baseline: 1.2920x; 1.2920x over previous
#include <cuda_runtime.h>
#include <math.h>

#define N_ATOMS 4096
#define NG      128
#define QKV_LD  768

// Scratch (no allocations allowed)
__device__ float g_qkv[N_ATOMS * QKV_LD];   // per row: [0:256)=Q [256:512)=K [512:768)=V
__device__ float g_segsum[NG * 256];        // per-group summed attention output
__device__ float g_wct[256 * 256];          // Wct[f][j] = (Wo2 @ Wo1)^T
__device__ float g_bc[256];                 // bc = Wo2 @ bo1

__device__ __forceinline__ float to_tf32(float x) {
    asm("cvt.rna.tf32.f32 %0, %0;" : "+f"(x));
    return x;
}

__device__ __forceinline__ void mma_tf32(float c[4], const unsigned a[4], const unsigned b[2]) {
    asm volatile(
        "mma.sync.aligned.m16n8k8.row.col.f32.tf32.tf32.f32 "
        "{%0,%1,%2,%3}, {%4,%5,%6,%7}, {%8,%9}, {%0,%1,%2,%3};"
        : "+f"(c[0]), "+f"(c[1]), "+f"(c[2]), "+f"(c[3])
        : "r"(a[0]), "r"(a[1]), "r"(a[2]), "r"(a[3]), "r"(b[0]), "r"(b[1]));
}

__device__ __forceinline__ float silu(float v) {
    return __fdividef(v, 1.0f + __expf(-v));
}

// ---------------------------------------------------------------------------
// k1 mega-kernel (128 threads/block):
//   blocks [0,384)   : TF32 QKV projection, BM=128 BN=64 BK=32, 4 warps of 64x32
//   blocks [384,416) : fp32 Wct[f][j] = sum_k Wo1[k][f] * Wo2[j][k]   (32f x 64j tiles)
//   blocks [416,424) : bc[j] = Wo2[j,:].bo1   +  zero g_segsum
// ---------------------------------------------------------------------------
#define PROJ_BLOCKS 384
#define WC_BLOCKS   32
#define K1_BLOCKS   (PROJ_BLOCKS + WC_BLOCKS + 8)
#define PP          40      // proj smem pitch (floats): conflict-free LDS.64 frags

__global__ __launch_bounds__(128) void k1(
        const float* __restrict__ x,
        const float* __restrict__ Wq, const float* __restrict__ bq,
        const float* __restrict__ Wk, const float* __restrict__ bk,
        const float* __restrict__ Wv, const float* __restrict__ bv,
        const float* __restrict__ Wo1, const float* __restrict__ bo1,
        const float* __restrict__ Wo2)
{
    __shared__ float sh[7680];      // proj: As 128*40 + Bs 64*40 = 7680 floats
    const int bid = blockIdx.x;
    const int tid = threadIdx.x;

    if (bid < PROJ_BLOCKS) {
        // ---------------- TF32 projection ----------------
        // smem k-layout per row, per 8-group: position p(k) = (k&3)*2 + ((k>>2)&1)
        // so the mma k-pair (tig, tig+4) is a contiguous float2 at column
        // group*8 + 2*tig.  Pitch 40 == 8 (mod 32) -> conflict-free LDS.64.
        float (*As)[PP] = (float(*)[PP])sh;              // [128][40]
        float (*Bs)[PP] = (float(*)[PP])(sh + 128 * PP); // [64][40]

        const int warp = tid >> 5;
        const int lane = tid & 31;
        const int grp  = lane >> 2;     // 0..7
        const int tig  = lane & 3;      // 0..3
        const int wm   = warp >> 1;     // 0..1 -> rows wm*64
        const int wn   = warp & 1;      // 0..1 -> cols wn*32

        const int n0 = (bid / 12) * 128;
        const int j0 = (bid % 12) * 64;
        const int sel = j0 >> 8;
        const float* __restrict__ W = (sel == 0) ? Wq : (sel == 1 ? Wk : Wv);
        const float* __restrict__ b = (sel == 0) ? bq : (sel == 1 ? bk : bv);
        const int jl = j0 & 255;

        float c[4][4][4] = {};   // [mt][nt][reg]

        for (int k0 = 0; k0 < 256; k0 += 32) {
            // A tile 128x32 -> 8 float4/thread, permuted scatter
            #pragma unroll
            for (int it = 0; it < 8; it++) {
                int lin = tid + it * 128;
                int row = lin >> 3;
                int cc  = lin & 7;          // float4 chunk (k = cc*4 + j)
                float4 a = *(const float4*)&x[(n0 + row) * 256 + k0 + cc * 4];
                int base = (cc >> 1) * 8 + (cc & 1);
                As[row][base + 0] = to_tf32(a.x);
                As[row][base + 2] = to_tf32(a.y);
                As[row][base + 4] = to_tf32(a.z);
                As[row][base + 6] = to_tf32(a.w);
            }
            // B tile 64x32 -> 4 float4/thread
            #pragma unroll
            for (int it = 0; it < 4; it++) {
                int lin = tid + it * 128;
                int row = lin >> 3;
                int cc  = lin & 7;
                float4 w = *(const float4*)&W[(jl + row) * 256 + k0 + cc * 4];
                int base = (cc >> 1) * 8 + (cc & 1);
                Bs[row][base + 0] = to_tf32(w.x);
                Bs[row][base + 2] = to_tf32(w.y);
                Bs[row][base + 4] = to_tf32(w.z);
                Bs[row][base + 6] = to_tf32(w.w);
            }
            __syncthreads();

            #pragma unroll
            for (int ks = 0; ks < 4; ks++) {
                const int kp = ks * 8 + 2 * tig;   // permuted column of the k-pair
                unsigned bf[4][2];
                #pragma unroll
                for (int nt = 0; nt < 4; nt++) {
                    float2 pB = *(const float2*)&Bs[wn * 32 + nt * 8 + grp][kp];
                    bf[nt][0] = __float_as_uint(pB.x);
                    bf[nt][1] = __float_as_uint(pB.y);
                }
                #pragma unroll
                for (int mt = 0; mt < 4; mt++) {
                    int rb = wm * 64 + mt * 16 + grp;
                    float2 pA0 = *(const float2*)&As[rb    ][kp];
                    float2 pA1 = *(const float2*)&As[rb + 8][kp];
                    unsigned af[4];
                    af[0] = __float_as_uint(pA0.x);
                    af[1] = __float_as_uint(pA1.x);
                    af[2] = __float_as_uint(pA0.y);
                    af[3] = __float_as_uint(pA1.y);
                    #pragma unroll
                    for (int nt = 0; nt < 4; nt++)
                        mma_tf32(c[mt][nt], af, bf[nt]);
                }
            }
            __syncthreads();
        }

        // epilogue
        #pragma unroll
        for (int mt = 0; mt < 4; mt++) {
            int r0 = n0 + wm * 64 + mt * 16 + grp;
            int r1 = r0 + 8;
            #pragma unroll
            for (int nt = 0; nt < 4; nt++) {
                int jj  = j0 + wn * 32 + nt * 8 + tig * 2;
                int jlb = jl + wn * 32 + nt * 8 + tig * 2;
                float b0 = b[jlb], b1 = b[jlb + 1];
                *(float2*)&g_qkv[r0 * QKV_LD + jj] = make_float2(c[mt][nt][0] + b0, c[mt][nt][1] + b1);
                *(float2*)&g_qkv[r1 * QKV_LD + jj] = make_float2(c[mt][nt][2] + b0, c[mt][nt][3] + b1);
            }
        }
    } else if (bid < PROJ_BLOCKS + WC_BLOCKS) {
        // ---------------- fp32 Wct tile: 32 f-rows x 64 j-cols, 128 threads --------
        float (*As)[36] = (float(*)[36])sh;              // As[kk][ff] = Wo1[k0+kk][f0+ff]
        float (*Bs)[68] = (float(*)[68])(sh + 32 * 36);  // Bs[kk][jj] = Wo2[j0+jj][k0+kk]

        const int t  = bid - PROJ_BLOCKS;
        const int f0 = (t >> 2) * 32;
        const int j0 = (t & 3) * 64;
        const int ti = tid >> 3;    // 0..15 -> f rows ti*2
        const int tj = tid & 7;     // 0..7  -> j cols tj*8

        float acc[2][8] = {};

        for (int k0 = 0; k0 < 256; k0 += 32) {
            #pragma unroll
            for (int it = 0; it < 2; it++) {
                int lin = tid + it * 128;
                int kk = lin >> 3;
                int fq = lin & 7;
                float4 a = *(const float4*)&Wo1[(k0 + kk) * 256 + f0 + fq * 4];
                *(float4*)&As[kk][fq * 4] = a;
            }
            #pragma unroll
            for (int it = 0; it < 4; it++) {
                int lin = tid + it * 128;
                int jj = lin >> 3;
                int kq = lin & 7;
                float4 w = *(const float4*)&Wo2[(j0 + jj) * 256 + k0 + kq * 4];
                Bs[kq * 4 + 0][jj] = w.x;
                Bs[kq * 4 + 1][jj] = w.y;
                Bs[kq * 4 + 2][jj] = w.z;
                Bs[kq * 4 + 3][jj] = w.w;
            }
            __syncthreads();
            #pragma unroll
            for (int kk = 0; kk < 32; kk++) {
                float2 a2 = *(const float2*)&As[kk][ti * 2];
                float4 b4a = *(const float4*)&Bs[kk][tj * 8];
                float4 b4b = *(const float4*)&Bs[kk][tj * 8 + 4];
                acc[0][0] += a2.x * b4a.x; acc[0][1] += a2.x * b4a.y;
                acc[0][2] += a2.x * b4a.z; acc[0][3] += a2.x * b4a.w;
                acc[0][4] += a2.x * b4b.x; acc[0][5] += a2.x * b4b.y;
                acc[0][6] += a2.x * b4b.z; acc[0][7] += a2.x * b4b.w;
                acc[1][0] += a2.y * b4a.x; acc[1][1] += a2.y * b4a.y;
                acc[1][2] += a2.y * b4a.z; acc[1][3] += a2.y * b4a.w;
                acc[1][4] += a2.y * b4b.x; acc[1][5] += a2.y * b4b.y;
                acc[1][6] += a2.y * b4b.z; acc[1][7] += a2.y * b4b.w;
            }
            __syncthreads();
        }
        #pragma unroll
        for (int u = 0; u < 2; u++)
            #pragma unroll
            for (int v = 0; v < 8; v++)
                g_wct[(f0 + ti * 2 + u) * 256 + j0 + tj * 8 + v] = acc[u][v];
    } else {
        // ---------------- bc[j] = Wo2[j,:].bo1  +  zero g_segsum ----------------
        const int bb   = bid - PROJ_BLOCKS - WC_BLOCKS;   // 0..7
        const int w    = tid >> 5;
        const int lane = tid & 31;
        #pragma unroll
        for (int u = 0; u < 8; u++) {
            int j = bb * 32 + w * 8 + u;
            float s = 0.0f;
            #pragma unroll
            for (int kc = 0; kc < 8; kc++) {
                int k = kc * 32 + lane;
                s += Wo2[j * 256 + k] * bo1[k];
            }
            #pragma unroll
            for (int off = 16; off; off >>= 1)
                s += __shfl_xor_sync(0xffffffffu, s, off);
            if (lane == 0) g_bc[j] = s;
        }
        // zero segsum: 32768 floats / 8 blocks = 4096 per block
        float4 z = make_float4(0.f, 0.f, 0.f, 0.f);
        #pragma unroll
        for (int it = 0; it < 8; it++)
            *(float4*)&g_segsum[bb * 4096 + it * 512 + tid * 4] = z;
    }
}

// ---------------------------------------------------------------------------
// Block-diagonal attention + fused segment-sum (R2 proven design).
// One block per row n; 8 warps = 8 heads; lane = head dim.
// ---------------------------------------------------------------------------
__global__ __launch_bounds__(256) void attn_kernel(const int* __restrict__ seg)
{
    __shared__ int s_start, s_end, s_g;
    const int n   = blockIdx.x;
    const int tid = threadIdx.x;

    if (tid == 0) {
        int gid = seg[n];
        s_g = gid;
        int lo = 0, hi = N_ATOMS;
        while (lo < hi) { int mid = (lo + hi) >> 1; if (seg[mid] < gid) lo = mid + 1; else hi = mid; }
        s_start = lo;
        lo = n + 1; hi = N_ATOMS;
        while (lo < hi) { int mid = (lo + hi) >> 1; if (seg[mid] <= gid) lo = mid + 1; else hi = mid; }
        s_end = lo;
    }
    __syncthreads();

    const int h    = tid >> 5;
    const int lane = tid & 31;
    const int col  = h * 32 + lane;

    const float q = g_qkv[n * QKV_LD + col];
    float acc = 0.0f;
    const int start = s_start, end = s_end, gid = s_g;

    #pragma unroll 2
    for (int m = start; m < end; m++) {
        float kd = __ldg(&g_qkv[m * QKV_LD + 256 + col]);
        float vd = __ldg(&g_qkv[m * QKV_LD + 512 + col]);
        float p = q * kd;
        #pragma unroll
        for (int off = 16; off; off >>= 1)
            p += __shfl_xor_sync(0xffffffffu, p, off);
        float s = silu(p);
        acc += s * vd;
    }
    atomicAdd(&g_segsum[gid * 256 + col], acc);
}

// ---------------------------------------------------------------------------
// Final: out[g][j] = silu( sum_f segsum[g][f]*Wct[f][j] + cnt_g*bc[j] + bo2[j] )
// 32 blocks x 256 threads; thread = column j, 4 g-rows per block.
// ---------------------------------------------------------------------------
__global__ __launch_bounds__(256) void final_kernel(
        const int* __restrict__ seg, const float* __restrict__ bo2,
        float* __restrict__ out)
{
    __shared__ float4 a4[256];
    __shared__ float s_cnt[4];

    const int g0  = blockIdx.x * 4;
    const int tid = threadIdx.x;

    float4 v;
    v.x = g_segsum[(g0 + 0) * 256 + tid];
    v.y = g_segsum[(g0 + 1) * 256 + tid];
    v.z = g_segsum[(g0 + 2) * 256 + tid];
    v.w = g_segsum[(g0 + 3) * 256 + tid];
    a4[tid] = v;

    if (tid < 4) {
        int g = g0 + tid;
        int lo = 0, hi = N_ATOMS;
        while (lo < hi) { int mid = (lo + hi) >> 1; if (seg[mid] < g) lo = mid + 1; else hi = mid; }
        int st = lo;
        hi = N_ATOMS;
        while (lo < hi) { int mid = (lo + hi) >> 1; if (seg[mid] <= g) lo = mid + 1; else hi = mid; }
        s_cnt[tid] = (float)(lo - st);
    }
    __syncthreads();

    float acc0 = 0.f, acc1 = 0.f, acc2 = 0.f, acc3 = 0.f;
    #pragma unroll 16
    for (int f = 0; f < 256; f++) {
        float wv = g_wct[f * 256 + tid];
        float4 a = a4[f];
        acc0 += a.x * wv;
        acc1 += a.y * wv;
        acc2 += a.z * wv;
        acc3 += a.w * wv;
    }

    float bcv = g_bc[tid];
    float b2  = bo2[tid];
    out[(g0 + 0) * 256 + tid] = silu(acc0 + s_cnt[0] * bcv + b2);
    out[(g0 + 1) * 256 + tid] = silu(acc1 + s_cnt[1] * bcv + b2);
    out[(g0 + 2) * 256 + tid] = silu(acc2 + s_cnt[2] * bcv + b2);
    out[(g0 + 3) * 256 + tid] = silu(acc3 + s_cnt[3] * bcv + b2);
}

// ---------------------------------------------------------------------------
extern "C" void kernel_launch(void* const* d_in, const int* in_sizes, int n_in,
                              void* d_out, int out_size)
{
    const float* x    = (const float*)d_in[0];
    const int*   elem = (const int*)d_in[1];
    const int*   seg  = elem + N_ATOMS;        // elem_index[1]
    const float* Wq   = (const float*)d_in[2];
    const float* bq   = (const float*)d_in[3];
    const float* Wk   = (const float*)d_in[4];
    const float* bk   = (const float*)d_in[5];
    const float* Wv   = (const float*)d_in[6];
    const float* bv   = (const float*)d_in[7];
    const float* Wo1  = (const float*)d_in[8];
    const float* bo1  = (const float*)d_in[9];
    const float* Wo2  = (const float*)d_in[10];
    const float* bo2  = (const float*)d_in[11];
    float* out = (float*)d_out;

    k1<<<K1_BLOCKS, 128>>>(x, Wq, bq, Wk, bk, Wv, bv, Wo1, bo1, Wo2);
    attn_kernel<<<N_ATOMS, 256>>>(seg);
    final_kernel<<<32, 256>>>(seg, bo2, out);
}

// round 5
// speedup vs baseline: 1.8239x; 1.4117x over previous
#include <cuda_runtime.h>
#include <math.h>

#define N_ATOMS 4096
#define NG      128
#define QKV_LD  768
#define CHUNK   64

// Scratch (no allocations allowed)
__device__ float g_qkv[N_ATOMS * QKV_LD];   // per row: [0:256)=Q [256:512)=K [512:768)=V
__device__ float g_segsum[NG * 256];        // per-group summed attention output
__device__ float g_wct[256 * 256];          // Wct[f][j] = (Wo2 @ Wo1)^T
__device__ float g_bc[256];                 // bc = Wo2 @ bo1

__device__ __forceinline__ float to_tf32(float x) {
    asm("cvt.rna.tf32.f32 %0, %0;" : "+f"(x));
    return x;
}

__device__ __forceinline__ void mma_tf32(float c[4], const unsigned a[4], const unsigned b[2]) {
    asm volatile(
        "mma.sync.aligned.m16n8k8.row.col.f32.tf32.tf32.f32 "
        "{%0,%1,%2,%3}, {%4,%5,%6,%7}, {%8,%9}, {%0,%1,%2,%3};"
        : "+f"(c[0]), "+f"(c[1]), "+f"(c[2]), "+f"(c[3])
        : "r"(a[0]), "r"(a[1]), "r"(a[2]), "r"(a[3]), "r"(b[0]), "r"(b[1]));
}

__device__ __forceinline__ float silu(float v) {
    return __fdividef(v, 1.0f + __expf(-v));
}

// ---------------------------------------------------------------------------
// k1 mega-kernel (128 threads/block):
//   blocks [0,384)   : TF32 QKV projection, BM=128 BN=64 BK=32, 4 warps of 64x32
//   blocks [384,416) : fp32 Wct[f][j] = sum_k Wo1[k][f] * Wo2[j][k]
//   blocks [416,424) : bc[j] = Wo2[j,:].bo1
// ---------------------------------------------------------------------------
#define PROJ_BLOCKS 384
#define WC_BLOCKS   32
#define K1_BLOCKS   (PROJ_BLOCKS + WC_BLOCKS + 8)
#define PP          40      // proj smem pitch (floats): conflict-free LDS.64 frags

__global__ __launch_bounds__(128) void k1(
        const float* __restrict__ x,
        const float* __restrict__ Wq, const float* __restrict__ bq,
        const float* __restrict__ Wk, const float* __restrict__ bk,
        const float* __restrict__ Wv, const float* __restrict__ bv,
        const float* __restrict__ Wo1, const float* __restrict__ bo1,
        const float* __restrict__ Wo2)
{
    __shared__ float sh[7680];
    const int bid = blockIdx.x;
    const int tid = threadIdx.x;

    if (bid < PROJ_BLOCKS) {
        // ---------------- TF32 projection ----------------
        float (*As)[PP] = (float(*)[PP])sh;              // [128][40]
        float (*Bs)[PP] = (float(*)[PP])(sh + 128 * PP); // [64][40]

        const int warp = tid >> 5;
        const int lane = tid & 31;
        const int grp  = lane >> 2;
        const int tig  = lane & 3;
        const int wm   = warp >> 1;
        const int wn   = warp & 1;

        const int n0 = (bid / 12) * 128;
        const int j0 = (bid % 12) * 64;
        const int sel = j0 >> 8;
        const float* __restrict__ W = (sel == 0) ? Wq : (sel == 1 ? Wk : Wv);
        const float* __restrict__ b = (sel == 0) ? bq : (sel == 1 ? bk : bv);
        const int jl = j0 & 255;

        float c[4][4][4] = {};

        for (int k0 = 0; k0 < 256; k0 += 32) {
            #pragma unroll
            for (int it = 0; it < 8; it++) {
                int lin = tid + it * 128;
                int row = lin >> 3;
                int cc  = lin & 7;
                float4 a = *(const float4*)&x[(n0 + row) * 256 + k0 + cc * 4];
                int base = (cc >> 1) * 8 + (cc & 1);
                As[row][base + 0] = to_tf32(a.x);
                As[row][base + 2] = to_tf32(a.y);
                As[row][base + 4] = to_tf32(a.z);
                As[row][base + 6] = to_tf32(a.w);
            }
            #pragma unroll
            for (int it = 0; it < 4; it++) {
                int lin = tid + it * 128;
                int row = lin >> 3;
                int cc  = lin & 7;
                float4 w = *(const float4*)&W[(jl + row) * 256 + k0 + cc * 4];
                int base = (cc >> 1) * 8 + (cc & 1);
                Bs[row][base + 0] = to_tf32(w.x);
                Bs[row][base + 2] = to_tf32(w.y);
                Bs[row][base + 4] = to_tf32(w.z);
                Bs[row][base + 6] = to_tf32(w.w);
            }
            __syncthreads();

            #pragma unroll
            for (int ks = 0; ks < 4; ks++) {
                const int kp = ks * 8 + 2 * tig;
                unsigned bf[4][2];
                #pragma unroll
                for (int nt = 0; nt < 4; nt++) {
                    float2 pB = *(const float2*)&Bs[wn * 32 + nt * 8 + grp][kp];
                    bf[nt][0] = __float_as_uint(pB.x);
                    bf[nt][1] = __float_as_uint(pB.y);
                }
                #pragma unroll
                for (int mt = 0; mt < 4; mt++) {
                    int rb = wm * 64 + mt * 16 + grp;
                    float2 pA0 = *(const float2*)&As[rb    ][kp];
                    float2 pA1 = *(const float2*)&As[rb + 8][kp];
                    unsigned af[4];
                    af[0] = __float_as_uint(pA0.x);
                    af[1] = __float_as_uint(pA1.x);
                    af[2] = __float_as_uint(pA0.y);
                    af[3] = __float_as_uint(pA1.y);
                    #pragma unroll
                    for (int nt = 0; nt < 4; nt++)
                        mma_tf32(c[mt][nt], af, bf[nt]);
                }
            }
            __syncthreads();
        }

        #pragma unroll
        for (int mt = 0; mt < 4; mt++) {
            int r0 = n0 + wm * 64 + mt * 16 + grp;
            int r1 = r0 + 8;
            #pragma unroll
            for (int nt = 0; nt < 4; nt++) {
                int jj  = j0 + wn * 32 + nt * 8 + tig * 2;
                int jlb = jl + wn * 32 + nt * 8 + tig * 2;
                float b0 = b[jlb], b1 = b[jlb + 1];
                *(float2*)&g_qkv[r0 * QKV_LD + jj] = make_float2(c[mt][nt][0] + b0, c[mt][nt][1] + b1);
                *(float2*)&g_qkv[r1 * QKV_LD + jj] = make_float2(c[mt][nt][2] + b0, c[mt][nt][3] + b1);
            }
        }
    } else if (bid < PROJ_BLOCKS + WC_BLOCKS) {
        // ---------------- fp32 Wct tile: 32 f-rows x 64 j-cols ----------------
        float (*As)[36] = (float(*)[36])sh;
        float (*Bs)[68] = (float(*)[68])(sh + 32 * 36);

        const int t  = bid - PROJ_BLOCKS;
        const int f0 = (t >> 2) * 32;
        const int j0 = (t & 3) * 64;
        const int ti = tid >> 3;
        const int tj = tid & 7;

        float acc[2][8] = {};

        for (int k0 = 0; k0 < 256; k0 += 32) {
            #pragma unroll
            for (int it = 0; it < 2; it++) {
                int lin = tid + it * 128;
                int kk = lin >> 3;
                int fq = lin & 7;
                float4 a = *(const float4*)&Wo1[(k0 + kk) * 256 + f0 + fq * 4];
                *(float4*)&As[kk][fq * 4] = a;
            }
            #pragma unroll
            for (int it = 0; it < 4; it++) {
                int lin = tid + it * 128;
                int jj = lin >> 3;
                int kq = lin & 7;
                float4 w = *(const float4*)&Wo2[(j0 + jj) * 256 + k0 + kq * 4];
                Bs[kq * 4 + 0][jj] = w.x;
                Bs[kq * 4 + 1][jj] = w.y;
                Bs[kq * 4 + 2][jj] = w.z;
                Bs[kq * 4 + 3][jj] = w.w;
            }
            __syncthreads();
            #pragma unroll
            for (int kk = 0; kk < 32; kk++) {
                float2 a2 = *(const float2*)&As[kk][ti * 2];
                float4 b4a = *(const float4*)&Bs[kk][tj * 8];
                float4 b4b = *(const float4*)&Bs[kk][tj * 8 + 4];
                acc[0][0] += a2.x * b4a.x; acc[0][1] += a2.x * b4a.y;
                acc[0][2] += a2.x * b4a.z; acc[0][3] += a2.x * b4a.w;
                acc[0][4] += a2.x * b4b.x; acc[0][5] += a2.x * b4b.y;
                acc[0][6] += a2.x * b4b.z; acc[0][7] += a2.x * b4b.w;
                acc[1][0] += a2.y * b4a.x; acc[1][1] += a2.y * b4a.y;
                acc[1][2] += a2.y * b4a.z; acc[1][3] += a2.y * b4a.w;
                acc[1][4] += a2.y * b4b.x; acc[1][5] += a2.y * b4b.y;
                acc[1][6] += a2.y * b4b.z; acc[1][7] += a2.y * b4b.w;
            }
            __syncthreads();
        }
        #pragma unroll
        for (int u = 0; u < 2; u++)
            #pragma unroll
            for (int v = 0; v < 8; v++)
                g_wct[(f0 + ti * 2 + u) * 256 + j0 + tj * 8 + v] = acc[u][v];
    } else {
        // ---------------- bc[j] = Wo2[j,:].bo1 ----------------
        const int bb   = bid - PROJ_BLOCKS - WC_BLOCKS;   // 0..7
        const int w    = tid >> 5;
        const int lane = tid & 31;
        #pragma unroll
        for (int u = 0; u < 8; u++) {
            int j = bb * 32 + w * 8 + u;
            float s = 0.0f;
            #pragma unroll
            for (int kc = 0; kc < 8; kc++) {
                int k = kc * 32 + lane;
                s += Wo2[j * 256 + k] * bo1[k];
            }
            #pragma unroll
            for (int off = 16; off; off >>= 1)
                s += __shfl_xor_sync(0xffffffffu, s, off);
            if (lane == 0) g_bc[j] = s;
        }
    }
}

// ---------------------------------------------------------------------------
// Attention via segsum linearity: block = (group, head), 256 threads.
//   T[m] = sum_n silu(q_n . k_m)   (shuffle-reduce once per m, not per (n,m))
//   segsum[g, h*32+d] = sum_m T[m] * v_m[d]
// No global atomics (block owns its 32 outputs), no inner-loop barriers.
// ---------------------------------------------------------------------------
__global__ __launch_bounds__(256) void attn_kernel(const int* __restrict__ seg)
{
    __shared__ float Qs[CHUNK][33];
    __shared__ float Ks[CHUNK][33];
    __shared__ float Vs[CHUNK][33];
    __shared__ float T[CHUNK];
    __shared__ float s_out[8][32];
    __shared__ int sb[2];

    const int g    = blockIdx.x;
    const int h    = blockIdx.y;
    const int tid  = threadIdx.x;
    const int w    = tid >> 5;
    const int lane = tid & 31;
    const int colbase = h * 32;

    if (tid == 0) {
        int lo = 0, hi = N_ATOMS;
        while (lo < hi) { int mid = (lo + hi) >> 1; if (seg[mid] < g) lo = mid + 1; else hi = mid; }
        sb[0] = lo;
        int hi2 = N_ATOMS;
        while (lo < hi2) { int mid = (lo + hi2) >> 1; if (seg[mid] <= g) lo = mid + 1; else hi2 = mid; }
        sb[1] = lo;
    }
    __syncthreads();
    const int start = sb[0], end = sb[1];

    float out_acc = 0.0f;

    for (int mc = start; mc < end; mc += CHUNK) {
        const int lm = min(CHUNK, end - mc);
        // stage K,V chunk (coalesced 128B rows)
        for (int idx = tid; idx < lm * 32; idx += 256) {
            int r = idx >> 5, d = idx & 31;
            Ks[r][d] = g_qkv[(mc + r) * QKV_LD + 256 + colbase + d];
            Vs[r][d] = g_qkv[(mc + r) * QKV_LD + 512 + colbase + d];
        }
        if (tid < CHUNK) T[tid] = 0.0f;
        __syncthreads();

        for (int nc = start; nc < end; nc += CHUNK) {
            const int ln = min(CHUNK, end - nc);
            for (int idx = tid; idx < ln * 32; idx += 256) {
                int r = idx >> 5, d = idx & 31;
                Qs[r][d] = g_qkv[(nc + r) * QKV_LD + colbase + d];
            }
            __syncthreads();

            for (int nb = 0; nb < ln; nb += 32) {
                const int n = nb + lane;
                const bool valid = n < ln;
                const int nn = valid ? n : 0;
                float qr[32];
                #pragma unroll
                for (int d = 0; d < 32; d++)
                    qr[d] = valid ? Qs[nn][d] : 0.0f;   // invalid lanes: dot=0 -> silu(0)=0

                for (int m = w; m < lm; m += 8) {
                    float dot = 0.0f;
                    #pragma unroll
                    for (int d = 0; d < 32; d++)
                        dot += qr[d] * Ks[m][d];        // Ks broadcast across lanes
                    float t = silu(dot);
                    #pragma unroll
                    for (int off = 16; off; off >>= 1)
                        t += __shfl_xor_sync(0xffffffffu, t, off);
                    if (lane == 0) T[m] += t;           // warp w owns m ≡ w (mod 8)
                }
            }
            __syncthreads();
        }

        // out[d] += sum_m T[m] * V[m][d]; warp w reads only the m's it wrote
        for (int m = w; m < lm; m += 8)
            out_acc += T[m] * Vs[m][lane];
        __syncthreads();
    }

    s_out[w][lane] = out_acc;
    __syncthreads();
    if (w == 0) {
        float s = s_out[0][lane];
        #pragma unroll
        for (int i = 1; i < 8; i++) s += s_out[i][lane];
        g_segsum[g * 256 + colbase + lane] = s;
    }
}

// ---------------------------------------------------------------------------
// Final: out[g][j] = silu( sum_f segsum[g][f]*Wct[f][j] + cnt_g*bc[j] + bo2[j] )
// 128 blocks (one group each) x 256 threads (one column each).
// ---------------------------------------------------------------------------
__global__ __launch_bounds__(256) void final_kernel(
        const int* __restrict__ seg, const float* __restrict__ bo2,
        float* __restrict__ out)
{
    __shared__ float a_sh[256];
    __shared__ float s_cnt;

    const int g   = blockIdx.x;
    const int tid = threadIdx.x;

    a_sh[tid] = g_segsum[g * 256 + tid];
    if (tid == 0) {
        int lo = 0, hi = N_ATOMS;
        while (lo < hi) { int mid = (lo + hi) >> 1; if (seg[mid] < g) lo = mid + 1; else hi = mid; }
        int st = lo;
        hi = N_ATOMS;
        while (lo < hi) { int mid = (lo + hi) >> 1; if (seg[mid] <= g) lo = mid + 1; else hi = mid; }
        s_cnt = (float)(lo - st);
    }
    __syncthreads();

    float acc = 0.0f;
    #pragma unroll 8
    for (int f = 0; f < 256; f++)
        acc += a_sh[f] * g_wct[f * 256 + tid];

    out[g * 256 + tid] = silu(acc + s_cnt * g_bc[tid] + bo2[tid]);
}

// ---------------------------------------------------------------------------
extern "C" void kernel_launch(void* const* d_in, const int* in_sizes, int n_in,
                              void* d_out, int out_size)
{
    const float* x    = (const float*)d_in[0];
    const int*   elem = (const int*)d_in[1];
    const int*   seg  = elem + N_ATOMS;        // elem_index[1]
    const float* Wq   = (const float*)d_in[2];
    const float* bq   = (const float*)d_in[3];
    const float* Wk   = (const float*)d_in[4];
    const float* bk   = (const float*)d_in[5];
    const float* Wv   = (const float*)d_in[6];
    const float* bv   = (const float*)d_in[7];
    const float* Wo1  = (const float*)d_in[8];
    const float* bo1  = (const float*)d_in[9];
    const float* Wo2  = (const float*)d_in[10];
    const float* bo2  = (const float*)d_in[11];
    float* out = (float*)d_out;

    k1<<<K1_BLOCKS, 128>>>(x, Wq, bq, Wk, bk, Wv, bv, Wo1, bo1, Wo2);
    attn_kernel<<<dim3(NG, 8), 256>>>(seg);
    final_kernel<<<NG, 256>>>(seg, bo2, out);
}

// round 6
// speedup vs baseline: 1.8725x; 1.0267x over previous
#include <cuda_runtime.h>
#include <math.h>

#define N_ATOMS 4096
#define NG      128
#define QKV_LD  768

// Scratch (no allocations allowed)
__device__ float g_qkv[N_ATOMS * QKV_LD];   // per row: [0:256)=Q [256:512)=K [512:768)=V
__device__ float g_wct[256 * 256];          // Wct[f][j] = (Wo2 @ Wo1)^T
__device__ float g_bc[256];                 // bc = Wo2 @ bo1

__device__ __forceinline__ float to_tf32(float x) {
    asm("cvt.rna.tf32.f32 %0, %0;" : "+f"(x));
    return x;
}

__device__ __forceinline__ void mma_tf32(float c[4], const unsigned a[4], const unsigned b[2]) {
    asm volatile(
        "mma.sync.aligned.m16n8k8.row.col.f32.tf32.tf32.f32 "
        "{%0,%1,%2,%3}, {%4,%5,%6,%7}, {%8,%9}, {%0,%1,%2,%3};"
        : "+f"(c[0]), "+f"(c[1]), "+f"(c[2]), "+f"(c[3])
        : "r"(a[0]), "r"(a[1]), "r"(a[2]), "r"(a[3]), "r"(b[0]), "r"(b[1]));
}

__device__ __forceinline__ float silu(float v) {
    return __fdividef(v, 1.0f + __expf(-v));
}

// ---------------------------------------------------------------------------
// k1 mega-kernel (128 threads/block):
//   blocks [0,384)   : TF32 QKV projection, BM=128 BN=64 BK=32, 4 warps of 64x32
//   blocks [384,416) : fp32 Wct[f][j] = sum_k Wo1[k][f] * Wo2[j][k]
//   blocks [416,424) : bc[j] = Wo2[j,:].bo1
// ---------------------------------------------------------------------------
#define PROJ_BLOCKS 384
#define WC_BLOCKS   32
#define K1_BLOCKS   (PROJ_BLOCKS + WC_BLOCKS + 8)
#define PP          40      // proj smem pitch (floats): conflict-free LDS.64 frags

__global__ __launch_bounds__(128) void k1(
        const float* __restrict__ x,
        const float* __restrict__ Wq, const float* __restrict__ bq,
        const float* __restrict__ Wk, const float* __restrict__ bk,
        const float* __restrict__ Wv, const float* __restrict__ bv,
        const float* __restrict__ Wo1, const float* __restrict__ bo1,
        const float* __restrict__ Wo2)
{
    __shared__ float sh[7680];
    const int bid = blockIdx.x;
    const int tid = threadIdx.x;

    if (bid < PROJ_BLOCKS) {
        // ---------------- TF32 projection ----------------
        float (*As)[PP] = (float(*)[PP])sh;              // [128][40]
        float (*Bs)[PP] = (float(*)[PP])(sh + 128 * PP); // [64][40]

        const int warp = tid >> 5;
        const int lane = tid & 31;
        const int grp  = lane >> 2;
        const int tig  = lane & 3;
        const int wm   = warp >> 1;
        const int wn   = warp & 1;

        const int n0 = (bid / 12) * 128;
        const int j0 = (bid % 12) * 64;
        const int sel = j0 >> 8;
        const float* __restrict__ W = (sel == 0) ? Wq : (sel == 1 ? Wk : Wv);
        const float* __restrict__ b = (sel == 0) ? bq : (sel == 1 ? bk : bv);
        const int jl = j0 & 255;

        float c[4][4][4] = {};

        for (int k0 = 0; k0 < 256; k0 += 32) {
            #pragma unroll
            for (int it = 0; it < 8; it++) {
                int lin = tid + it * 128;
                int row = lin >> 3;
                int cc  = lin & 7;
                float4 a = *(const float4*)&x[(n0 + row) * 256 + k0 + cc * 4];
                int base = (cc >> 1) * 8 + (cc & 1);
                As[row][base + 0] = to_tf32(a.x);
                As[row][base + 2] = to_tf32(a.y);
                As[row][base + 4] = to_tf32(a.z);
                As[row][base + 6] = to_tf32(a.w);
            }
            #pragma unroll
            for (int it = 0; it < 4; it++) {
                int lin = tid + it * 128;
                int row = lin >> 3;
                int cc  = lin & 7;
                float4 w = *(const float4*)&W[(jl + row) * 256 + k0 + cc * 4];
                int base = (cc >> 1) * 8 + (cc & 1);
                Bs[row][base + 0] = to_tf32(w.x);
                Bs[row][base + 2] = to_tf32(w.y);
                Bs[row][base + 4] = to_tf32(w.z);
                Bs[row][base + 6] = to_tf32(w.w);
            }
            __syncthreads();

            #pragma unroll
            for (int ks = 0; ks < 4; ks++) {
                const int kp = ks * 8 + 2 * tig;
                unsigned bf[4][2];
                #pragma unroll
                for (int nt = 0; nt < 4; nt++) {
                    float2 pB = *(const float2*)&Bs[wn * 32 + nt * 8 + grp][kp];
                    bf[nt][0] = __float_as_uint(pB.x);
                    bf[nt][1] = __float_as_uint(pB.y);
                }
                #pragma unroll
                for (int mt = 0; mt < 4; mt++) {
                    int rb = wm * 64 + mt * 16 + grp;
                    float2 pA0 = *(const float2*)&As[rb    ][kp];
                    float2 pA1 = *(const float2*)&As[rb + 8][kp];
                    unsigned af[4];
                    af[0] = __float_as_uint(pA0.x);
                    af[1] = __float_as_uint(pA1.x);
                    af[2] = __float_as_uint(pA0.y);
                    af[3] = __float_as_uint(pA1.y);
                    #pragma unroll
                    for (int nt = 0; nt < 4; nt++)
                        mma_tf32(c[mt][nt], af, bf[nt]);
                }
            }
            __syncthreads();
        }

        #pragma unroll
        for (int mt = 0; mt < 4; mt++) {
            int r0 = n0 + wm * 64 + mt * 16 + grp;
            int r1 = r0 + 8;
            #pragma unroll
            for (int nt = 0; nt < 4; nt++) {
                int jj  = j0 + wn * 32 + nt * 8 + tig * 2;
                int jlb = jl + wn * 32 + nt * 8 + tig * 2;
                float b0 = b[jlb], b1 = b[jlb + 1];
                *(float2*)&g_qkv[r0 * QKV_LD + jj] = make_float2(c[mt][nt][0] + b0, c[mt][nt][1] + b1);
                *(float2*)&g_qkv[r1 * QKV_LD + jj] = make_float2(c[mt][nt][2] + b0, c[mt][nt][3] + b1);
            }
        }
    } else if (bid < PROJ_BLOCKS + WC_BLOCKS) {
        // ---------------- fp32 Wct tile: 32 f-rows x 64 j-cols ----------------
        float (*As)[36] = (float(*)[36])sh;
        float (*Bs)[68] = (float(*)[68])(sh + 32 * 36);

        const int t  = bid - PROJ_BLOCKS;
        const int f0 = (t >> 2) * 32;
        const int j0 = (t & 3) * 64;
        const int ti = tid >> 3;
        const int tj = tid & 7;

        float acc[2][8] = {};

        for (int k0 = 0; k0 < 256; k0 += 32) {
            #pragma unroll
            for (int it = 0; it < 2; it++) {
                int lin = tid + it * 128;
                int kk = lin >> 3;
                int fq = lin & 7;
                float4 a = *(const float4*)&Wo1[(k0 + kk) * 256 + f0 + fq * 4];
                *(float4*)&As[kk][fq * 4] = a;
            }
            #pragma unroll
            for (int it = 0; it < 4; it++) {
                int lin = tid + it * 128;
                int jj = lin >> 3;
                int kq = lin & 7;
                float4 w = *(const float4*)&Wo2[(j0 + jj) * 256 + k0 + kq * 4];
                Bs[kq * 4 + 0][jj] = w.x;
                Bs[kq * 4 + 1][jj] = w.y;
                Bs[kq * 4 + 2][jj] = w.z;
                Bs[kq * 4 + 3][jj] = w.w;
            }
            __syncthreads();
            #pragma unroll
            for (int kk = 0; kk < 32; kk++) {
                float2 a2 = *(const float2*)&As[kk][ti * 2];
                float4 b4a = *(const float4*)&Bs[kk][tj * 8];
                float4 b4b = *(const float4*)&Bs[kk][tj * 8 + 4];
                acc[0][0] += a2.x * b4a.x; acc[0][1] += a2.x * b4a.y;
                acc[0][2] += a2.x * b4a.z; acc[0][3] += a2.x * b4a.w;
                acc[0][4] += a2.x * b4b.x; acc[0][5] += a2.x * b4b.y;
                acc[0][6] += a2.x * b4b.z; acc[0][7] += a2.x * b4b.w;
                acc[1][0] += a2.y * b4a.x; acc[1][1] += a2.y * b4a.y;
                acc[1][2] += a2.y * b4a.z; acc[1][3] += a2.y * b4a.w;
                acc[1][4] += a2.y * b4b.x; acc[1][5] += a2.y * b4b.y;
                acc[1][6] += a2.y * b4b.z; acc[1][7] += a2.y * b4b.w;
            }
            __syncthreads();
        }
        #pragma unroll
        for (int u = 0; u < 2; u++)
            #pragma unroll
            for (int v = 0; v < 8; v++)
                g_wct[(f0 + ti * 2 + u) * 256 + j0 + tj * 8 + v] = acc[u][v];
    } else {
        // ---------------- bc[j] = Wo2[j,:].bo1 ----------------
        const int bb   = bid - PROJ_BLOCKS - WC_BLOCKS;   // 0..7
        const int w    = tid >> 5;
        const int lane = tid & 31;
        #pragma unroll
        for (int u = 0; u < 8; u++) {
            int j = bb * 32 + w * 8 + u;
            float s = 0.0f;
            #pragma unroll
            for (int kc = 0; kc < 8; kc++) {
                int k = kc * 32 + lane;
                s += Wo2[j * 256 + k] * bo1[k];
            }
            #pragma unroll
            for (int off = 16; off; off >>= 1)
                s += __shfl_xor_sync(0xffffffffu, s, off);
            if (lane == 0) g_bc[j] = s;
        }
    }
}

// ---------------------------------------------------------------------------
// Fused attention + output projection. Block = group (8 warps = 8 heads).
//   T[m] = sum_n silu(k_m . q_n)    lane = m, k_m in registers, q_n broadcast
//                                    -> ZERO shuffles in the hot loop
//   seg[d] = sum_m T[m] * v_m[d]    (32 shuffles per 32-m chunk)
//   out[g][j] = silu( sum_f seg[f]*Wct[f][j] + cnt*bc[j] + bo2[j] )
// 32-row chunks, zero-padded (silu(0)=0 keeps chunked math exact).
// Dynamic smem: Q/K/V chunk [32][257] each + seg row.
// ---------------------------------------------------------------------------
#define APITCH 257
__global__ __launch_bounds__(256) void attn_final(
        const int* __restrict__ seg, const float* __restrict__ bo2,
        float* __restrict__ out)
{
    extern __shared__ float dsh[];
    float (*Qs)[APITCH] = (float(*)[APITCH])dsh;
    float (*Ks)[APITCH] = (float(*)[APITCH])(dsh + 32 * APITCH);
    float (*Vs)[APITCH] = (float(*)[APITCH])(dsh + 64 * APITCH);
    float* seg_sh = dsh + 96 * APITCH;
    __shared__ int sb[2];

    const int g    = blockIdx.x;
    const int tid  = threadIdx.x;
    const int h    = tid >> 5;         // warp = head
    const int lane = tid & 31;
    const int hb   = h * 32;

    if (tid == 0) {
        int lo = 0, hi = N_ATOMS;
        while (lo < hi) { int mid = (lo + hi) >> 1; if (seg[mid] < g) lo = mid + 1; else hi = mid; }
        sb[0] = lo;
        int hi2 = N_ATOMS;
        while (lo < hi2) { int mid = (lo + hi2) >> 1; if (seg[mid] <= g) lo = mid + 1; else hi2 = mid; }
        sb[1] = lo;
    }
    __syncthreads();
    const int start = sb[0], end = sb[1];
    const int L = end - start;

    float out_acc = 0.0f;
    const float4 z4 = make_float4(0.f, 0.f, 0.f, 0.f);

    for (int mc = 0; mc < L; mc += 32) {
        const int lm = min(32, L - mc);
        // stage K,V rows [mc, mc+32) — full 256-wide rows, coalesced float4
        #pragma unroll
        for (int it = 0; it < 8; it++) {
            int idx = tid + it * 256;      // 0..2047 float4 slots
            int r   = idx >> 6;            // 0..31
            int c4  = idx & 63;
            float4 kv = (r < lm) ? *(const float4*)&g_qkv[(start + mc + r) * QKV_LD + 256 + c4 * 4] : z4;
            float4 vv = (r < lm) ? *(const float4*)&g_qkv[(start + mc + r) * QKV_LD + 512 + c4 * 4] : z4;
            Ks[r][c4 * 4 + 0] = kv.x; Ks[r][c4 * 4 + 1] = kv.y;
            Ks[r][c4 * 4 + 2] = kv.z; Ks[r][c4 * 4 + 3] = kv.w;
            Vs[r][c4 * 4 + 0] = vv.x; Vs[r][c4 * 4 + 1] = vv.y;
            Vs[r][c4 * 4 + 2] = vv.z; Vs[r][c4 * 4 + 3] = vv.w;
        }
        __syncthreads();

        // lane m holds k_m[0..31] for its head (stride-257 column read: conflict-free)
        float kreg[32];
        #pragma unroll
        for (int d = 0; d < 32; d++)
            kreg[d] = Ks[lane][hb + d];

        float T = 0.0f;
        for (int nc = 0; nc < L; nc += 32) {
            const int ln = min(32, L - nc);
            #pragma unroll
            for (int it = 0; it < 8; it++) {
                int idx = tid + it * 256;
                int r   = idx >> 6;
                int c4  = idx & 63;
                float4 qv = (r < ln) ? *(const float4*)&g_qkv[(start + nc + r) * QKV_LD + c4 * 4] : z4;
                Qs[r][c4 * 4 + 0] = qv.x; Qs[r][c4 * 4 + 1] = qv.y;
                Qs[r][c4 * 4 + 2] = qv.z; Qs[r][c4 * 4 + 3] = qv.w;
            }
            __syncthreads();

            #pragma unroll 4
            for (int n = 0; n < 32; n++) {
                float dot = 0.0f;
                #pragma unroll
                for (int d = 0; d < 32; d++)
                    dot += kreg[d] * Qs[n][hb + d];    // broadcast LDS
                T += silu(dot);                         // zero-pad rows add silu(0)=0
            }
            __syncthreads();
        }

        // out[d] += sum_m T[m] * V[m][d]
        #pragma unroll
        for (int m = 0; m < 32; m++) {
            float tm = __shfl_sync(0xffffffffu, T, m);
            out_acc += tm * Vs[m][hb + lane];
        }
        __syncthreads();
    }

    seg_sh[hb + lane] = out_acc;
    __syncthreads();

    // fused output projection: thread = column j
    float acc = 0.0f;
    #pragma unroll 8
    for (int f = 0; f < 256; f++)
        acc += seg_sh[f] * g_wct[f * 256 + tid];

    out[g * 256 + tid] = silu(acc + (float)L * g_bc[tid] + bo2[tid]);
}

#define ATTN_SMEM ((96 * APITCH + 256) * 4)

// ---------------------------------------------------------------------------
extern "C" void kernel_launch(void* const* d_in, const int* in_sizes, int n_in,
                              void* d_out, int out_size)
{
    const float* x    = (const float*)d_in[0];
    const int*   elem = (const int*)d_in[1];
    const int*   seg  = elem + N_ATOMS;        // elem_index[1]
    const float* Wq   = (const float*)d_in[2];
    const float* bq   = (const float*)d_in[3];
    const float* Wk   = (const float*)d_in[4];
    const float* bk   = (const float*)d_in[5];
    const float* Wv   = (const float*)d_in[6];
    const float* bv   = (const float*)d_in[7];
    const float* Wo1  = (const float*)d_in[8];
    const float* bo1  = (const float*)d_in[9];
    const float* Wo2  = (const float*)d_in[10];
    const float* bo2  = (const float*)d_in[11];
    float* out = (float*)d_out;

    static bool attr_set = false;
    if (!attr_set) {
        cudaFuncSetAttribute(attn_final, cudaFuncAttributeMaxDynamicSharedMemorySize, ATTN_SMEM);
        attr_set = true;
    }

    k1<<<K1_BLOCKS, 128>>>(x, Wq, bq, Wk, bk, Wv, bv, Wo1, bo1, Wo2);
    attn_final<<<NG, 256, ATTN_SMEM>>>(seg, bo2, out);
}

// round 7
// speedup vs baseline: 2.1284x; 1.1366x over previous
#include <cuda_runtime.h>
#include <math.h>

#define N_ATOMS 4096
#define NG      128
#define QKV_LD  768

// Scratch (no allocations allowed)
__device__ float g_qkv[N_ATOMS * QKV_LD];   // per row: [0:256)=Q [256:512)=K [512:768)=V
__device__ float g_segsum[NG * 256];        // per-group attention segment sums
__device__ float g_wct[256 * 256];          // Wct[f][j] = (Wo2 @ Wo1)^T
__device__ float g_bc[256];                 // bc = Wo2 @ bo1
__device__ int   g_off[NG + 1];             // group start offsets (sorted seg ids)

__device__ __forceinline__ float to_tf32(float x) {
    asm("cvt.rna.tf32.f32 %0, %0;" : "+f"(x));
    return x;
}

__device__ __forceinline__ void mma_tf32(float c[4], const unsigned a[4], const unsigned b[2]) {
    asm volatile(
        "mma.sync.aligned.m16n8k8.row.col.f32.tf32.tf32.f32 "
        "{%0,%1,%2,%3}, {%4,%5,%6,%7}, {%8,%9}, {%0,%1,%2,%3};"
        : "+f"(c[0]), "+f"(c[1]), "+f"(c[2]), "+f"(c[3])
        : "r"(a[0]), "r"(a[1]), "r"(a[2]), "r"(a[3]), "r"(b[0]), "r"(b[1]));
}

__device__ __forceinline__ float silu(float v) {          // exact-ish (final layer)
    return __fdividef(v, 1.0f + __expf(-v));
}

__device__ __forceinline__ float silu_fast(float x) {     // 1 MUFU: x/2*(1+tanh(x/2))
    float h = 0.5f * x;
    float t;
    asm("tanh.approx.f32 %0, %1;" : "=f"(t) : "f"(h));
    return h + h * t;
}

// ---------------------------------------------------------------------------
// k1 mega-kernel (128 threads/block):
//   blocks [0,384)   : TF32 QKV projection, BM=128 BN=64 BK=32
//   blocks [384,416) : fp32 Wct[f][j] = sum_k Wo1[k][f] * Wo2[j][k]
//   blocks [416,424) : bc[j] = Wo2[j,:].bo1 ; block 416 also fills g_off[]
// ---------------------------------------------------------------------------
#define PROJ_BLOCKS 384
#define WC_BLOCKS   32
#define K1_BLOCKS   (PROJ_BLOCKS + WC_BLOCKS + 8)
#define PP          40

__global__ __launch_bounds__(128) void k1(
        const float* __restrict__ x,
        const float* __restrict__ Wq, const float* __restrict__ bq,
        const float* __restrict__ Wk, const float* __restrict__ bk,
        const float* __restrict__ Wv, const float* __restrict__ bv,
        const float* __restrict__ Wo1, const float* __restrict__ bo1,
        const float* __restrict__ Wo2, const int* __restrict__ seg)
{
    __shared__ float sh[7680];
    const int bid = blockIdx.x;
    const int tid = threadIdx.x;

    if (bid < PROJ_BLOCKS) {
        // ---------------- TF32 projection ----------------
        float (*As)[PP] = (float(*)[PP])sh;              // [128][40]
        float (*Bs)[PP] = (float(*)[PP])(sh + 128 * PP); // [64][40]

        const int warp = tid >> 5;
        const int lane = tid & 31;
        const int grp  = lane >> 2;
        const int tig  = lane & 3;
        const int wm   = warp >> 1;
        const int wn   = warp & 1;

        const int n0 = (bid / 12) * 128;
        const int j0 = (bid % 12) * 64;
        const int sel = j0 >> 8;
        const float* __restrict__ W = (sel == 0) ? Wq : (sel == 1 ? Wk : Wv);
        const float* __restrict__ b = (sel == 0) ? bq : (sel == 1 ? bk : bv);
        const int jl = j0 & 255;

        float c[4][4][4] = {};

        for (int k0 = 0; k0 < 256; k0 += 32) {
            #pragma unroll
            for (int it = 0; it < 8; it++) {
                int lin = tid + it * 128;
                int row = lin >> 3;
                int cc  = lin & 7;
                float4 a = *(const float4*)&x[(n0 + row) * 256 + k0 + cc * 4];
                int base = (cc >> 1) * 8 + (cc & 1);
                As[row][base + 0] = to_tf32(a.x);
                As[row][base + 2] = to_tf32(a.y);
                As[row][base + 4] = to_tf32(a.z);
                As[row][base + 6] = to_tf32(a.w);
            }
            #pragma unroll
            for (int it = 0; it < 4; it++) {
                int lin = tid + it * 128;
                int row = lin >> 3;
                int cc  = lin & 7;
                float4 w = *(const float4*)&W[(jl + row) * 256 + k0 + cc * 4];
                int base = (cc >> 1) * 8 + (cc & 1);
                Bs[row][base + 0] = to_tf32(w.x);
                Bs[row][base + 2] = to_tf32(w.y);
                Bs[row][base + 4] = to_tf32(w.z);
                Bs[row][base + 6] = to_tf32(w.w);
            }
            __syncthreads();

            #pragma unroll
            for (int ks = 0; ks < 4; ks++) {
                const int kp = ks * 8 + 2 * tig;
                unsigned bf[4][2];
                #pragma unroll
                for (int nt = 0; nt < 4; nt++) {
                    float2 pB = *(const float2*)&Bs[wn * 32 + nt * 8 + grp][kp];
                    bf[nt][0] = __float_as_uint(pB.x);
                    bf[nt][1] = __float_as_uint(pB.y);
                }
                #pragma unroll
                for (int mt = 0; mt < 4; mt++) {
                    int rb = wm * 64 + mt * 16 + grp;
                    float2 pA0 = *(const float2*)&As[rb    ][kp];
                    float2 pA1 = *(const float2*)&As[rb + 8][kp];
                    unsigned af[4];
                    af[0] = __float_as_uint(pA0.x);
                    af[1] = __float_as_uint(pA1.x);
                    af[2] = __float_as_uint(pA0.y);
                    af[3] = __float_as_uint(pA1.y);
                    #pragma unroll
                    for (int nt = 0; nt < 4; nt++)
                        mma_tf32(c[mt][nt], af, bf[nt]);
                }
            }
            __syncthreads();
        }

        #pragma unroll
        for (int mt = 0; mt < 4; mt++) {
            int r0 = n0 + wm * 64 + mt * 16 + grp;
            int r1 = r0 + 8;
            #pragma unroll
            for (int nt = 0; nt < 4; nt++) {
                int jj  = j0 + wn * 32 + nt * 8 + tig * 2;
                int jlb = jl + wn * 32 + nt * 8 + tig * 2;
                float b0 = b[jlb], b1 = b[jlb + 1];
                *(float2*)&g_qkv[r0 * QKV_LD + jj] = make_float2(c[mt][nt][0] + b0, c[mt][nt][1] + b1);
                *(float2*)&g_qkv[r1 * QKV_LD + jj] = make_float2(c[mt][nt][2] + b0, c[mt][nt][3] + b1);
            }
        }
    } else if (bid < PROJ_BLOCKS + WC_BLOCKS) {
        // ---------------- fp32 Wct tile: 32 f-rows x 64 j-cols ----------------
        float (*As)[36] = (float(*)[36])sh;
        float (*Bs)[68] = (float(*)[68])(sh + 32 * 36);

        const int t  = bid - PROJ_BLOCKS;
        const int f0 = (t >> 2) * 32;
        const int j0 = (t & 3) * 64;
        const int ti = tid >> 3;
        const int tj = tid & 7;

        float acc[2][8] = {};

        for (int k0 = 0; k0 < 256; k0 += 32) {
            #pragma unroll
            for (int it = 0; it < 2; it++) {
                int lin = tid + it * 128;
                int kk = lin >> 3;
                int fq = lin & 7;
                float4 a = *(const float4*)&Wo1[(k0 + kk) * 256 + f0 + fq * 4];
                *(float4*)&As[kk][fq * 4] = a;
            }
            #pragma unroll
            for (int it = 0; it < 4; it++) {
                int lin = tid + it * 128;
                int jj = lin >> 3;
                int kq = lin & 7;
                float4 w = *(const float4*)&Wo2[(j0 + jj) * 256 + k0 + kq * 4];
                Bs[kq * 4 + 0][jj] = w.x;
                Bs[kq * 4 + 1][jj] = w.y;
                Bs[kq * 4 + 2][jj] = w.z;
                Bs[kq * 4 + 3][jj] = w.w;
            }
            __syncthreads();
            #pragma unroll
            for (int kk = 0; kk < 32; kk++) {
                float2 a2 = *(const float2*)&As[kk][ti * 2];
                float4 b4a = *(const float4*)&Bs[kk][tj * 8];
                float4 b4b = *(const float4*)&Bs[kk][tj * 8 + 4];
                acc[0][0] += a2.x * b4a.x; acc[0][1] += a2.x * b4a.y;
                acc[0][2] += a2.x * b4a.z; acc[0][3] += a2.x * b4a.w;
                acc[0][4] += a2.x * b4b.x; acc[0][5] += a2.x * b4b.y;
                acc[0][6] += a2.x * b4b.z; acc[0][7] += a2.x * b4b.w;
                acc[1][0] += a2.y * b4a.x; acc[1][1] += a2.y * b4a.y;
                acc[1][2] += a2.y * b4a.z; acc[1][3] += a2.y * b4a.w;
                acc[1][4] += a2.y * b4b.x; acc[1][5] += a2.y * b4b.y;
                acc[1][6] += a2.y * b4b.z; acc[1][7] += a2.y * b4b.w;
            }
            __syncthreads();
        }
        #pragma unroll
        for (int u = 0; u < 2; u++)
            #pragma unroll
            for (int v = 0; v < 8; v++)
                g_wct[(f0 + ti * 2 + u) * 256 + j0 + tj * 8 + v] = acc[u][v];
    } else {
        // ---------------- bc[j] = Wo2[j,:].bo1 ; block 416: g_off ----------------
        const int bb   = bid - PROJ_BLOCKS - WC_BLOCKS;   // 0..7
        const int w    = tid >> 5;
        const int lane = tid & 31;
        #pragma unroll
        for (int u = 0; u < 8; u++) {
            int j = bb * 32 + w * 8 + u;
            float s = 0.0f;
            #pragma unroll
            for (int kc = 0; kc < 8; kc++) {
                int k = kc * 32 + lane;
                s += Wo2[j * 256 + k] * bo1[k];
            }
            #pragma unroll
            for (int off = 16; off; off >>= 1)
                s += __shfl_xor_sync(0xffffffffu, s, off);
            if (lane == 0) g_bc[j] = s;
        }
        if (bb == 0) {
            // g_off[g] = lower_bound(seg, g); one thread per group
            int g = tid;          // 0..127
            int lo = 0, hi = N_ATOMS;
            while (lo < hi) { int mid = (lo + hi) >> 1; if (seg[mid] < g) lo = mid + 1; else hi = mid; }
            g_off[g] = lo;
            if (tid == 0) g_off[NG] = N_ATOMS;
        }
    }
}

// ---------------------------------------------------------------------------
// Attention segment-sum. Block = (group, head), 128 threads = 4 warps.
//   T[m] = sum_n silu(k_m . q_n)  — lane = m (k_m in regs), n split over warps
//   segsum[d] = sum_m T[m] * v_m[d]  — m-ranges split over warps
// 13 KB smem -> many blocks/SM. Zero shuffles, zero atomics.
// ---------------------------------------------------------------------------
__global__ __launch_bounds__(128) void attn_kernel()
{
    __shared__ float Ks[32][33];
    __shared__ float Vs[32][33];
    __shared__ float Qs[32][33];
    __shared__ float Tsh[4][32];
    __shared__ float Osh[4][32];

    const int g    = blockIdx.x;
    const int h    = blockIdx.y;
    const int tid  = threadIdx.x;
    const int w    = tid >> 5;
    const int lane = tid & 31;
    const int hb   = h * 32;

    const int start = g_off[g];
    const int end   = g_off[g + 1];
    const int L     = end - start;

    float out_acc = 0.0f;
    const float4 z4 = make_float4(0.f, 0.f, 0.f, 0.f);

    for (int mc = 0; mc < L; mc += 32) {
        const int lm = min(32, L - mc);
        // stage K,V rows (32 x 32 floats each); 128 thr x 2 float4 per array
        #pragma unroll
        for (int it = 0; it < 2; it++) {
            int idx = tid + it * 128;      // 0..255 float4 slots
            int r   = idx >> 3;            // 0..31
            int c4  = idx & 7;
            float4 kv = (r < lm) ? *(const float4*)&g_qkv[(start + mc + r) * QKV_LD + 256 + hb + c4 * 4] : z4;
            float4 vv = (r < lm) ? *(const float4*)&g_qkv[(start + mc + r) * QKV_LD + 512 + hb + c4 * 4] : z4;
            Ks[r][c4 * 4 + 0] = kv.x; Ks[r][c4 * 4 + 1] = kv.y;
            Ks[r][c4 * 4 + 2] = kv.z; Ks[r][c4 * 4 + 3] = kv.w;
            Vs[r][c4 * 4 + 0] = vv.x; Vs[r][c4 * 4 + 1] = vv.y;
            Vs[r][c4 * 4 + 2] = vv.z; Vs[r][c4 * 4 + 3] = vv.w;
        }
        __syncthreads();

        // lane = m: k_m in registers (stride-33 column read, conflict-free)
        float kreg[32];
        #pragma unroll
        for (int d = 0; d < 32; d++)
            kreg[d] = Ks[lane][d];

        float T = 0.0f;       // partial over this warp's n subset
        for (int nc = 0; nc < L; nc += 32) {
            const int ln = min(32, L - nc);
            #pragma unroll
            for (int it = 0; it < 2; it++) {
                int idx = tid + it * 128;
                int r   = idx >> 3;
                int c4  = idx & 7;
                float4 qv = (r < ln) ? *(const float4*)&g_qkv[(start + nc + r) * QKV_LD + hb + c4 * 4] : z4;
                Qs[r][c4 * 4 + 0] = qv.x; Qs[r][c4 * 4 + 1] = qv.y;
                Qs[r][c4 * 4 + 2] = qv.z; Qs[r][c4 * 4 + 3] = qv.w;
            }
            __syncthreads();

            // warp w handles n in [w*8, min(w*8+8, ln))
            const int ncnt = max(0, min(8, ln - w * 8));
            for (int i = 0; i < ncnt; i++) {
                const int n = w * 8 + i;
                float d0 = 0.f, d1 = 0.f, d2 = 0.f, d3 = 0.f;
                #pragma unroll
                for (int d = 0; d < 8; d++) {
                    d0 += kreg[d     ] * Qs[n][d     ];
                    d1 += kreg[d +  8] * Qs[n][d +  8];
                    d2 += kreg[d + 16] * Qs[n][d + 16];
                    d3 += kreg[d + 24] * Qs[n][d + 24];
                }
                T += silu_fast((d0 + d1) + (d2 + d3));
            }
            __syncthreads();
        }

        Tsh[w][lane] = T;
        __syncthreads();

        // AV: warp w handles m in [w*8, w*8+8); T_tot[m] = sum_w Tsh[w][m]
        #pragma unroll
        for (int i = 0; i < 8; i++) {
            int m = w * 8 + i;
            float tm = Tsh[0][m] + Tsh[1][m] + Tsh[2][m] + Tsh[3][m];
            out_acc += tm * Vs[m][lane];
        }
        __syncthreads();
    }

    Osh[w][lane] = out_acc;
    __syncthreads();
    if (w == 0)
        g_segsum[g * 256 + hb + lane] =
            Osh[0][lane] + Osh[1][lane] + Osh[2][lane] + Osh[3][lane];
}

// ---------------------------------------------------------------------------
// Final: out[g][j] = silu( sum_f segsum[g][f]*Wct[f][j] + cnt_g*bc[j] + bo2[j] )
// 128 blocks x 256 threads (thread = column).
// ---------------------------------------------------------------------------
__global__ __launch_bounds__(256) void final_kernel(
        const float* __restrict__ bo2, float* __restrict__ out)
{
    __shared__ float a_sh[256];

    const int g   = blockIdx.x;
    const int tid = threadIdx.x;

    a_sh[tid] = g_segsum[g * 256 + tid];
    const float cnt = (float)(g_off[g + 1] - g_off[g]);
    __syncthreads();

    float acc = 0.0f;
    #pragma unroll 8
    for (int f = 0; f < 256; f++)
        acc += a_sh[f] * g_wct[f * 256 + tid];

    out[g * 256 + tid] = silu(acc + cnt * g_bc[tid] + bo2[tid]);
}

// ---------------------------------------------------------------------------
extern "C" void kernel_launch(void* const* d_in, const int* in_sizes, int n_in,
                              void* d_out, int out_size)
{
    const float* x    = (const float*)d_in[0];
    const int*   elem = (const int*)d_in[1];
    const int*   seg  = elem + N_ATOMS;        // elem_index[1]
    const float* Wq   = (const float*)d_in[2];
    const float* bq   = (const float*)d_in[3];
    const float* Wk   = (const float*)d_in[4];
    const float* bk   = (const float*)d_in[5];
    const float* Wv   = (const float*)d_in[6];
    const float* bv   = (const float*)d_in[7];
    const float* Wo1  = (const float*)d_in[8];
    const float* bo1  = (const float*)d_in[9];
    const float* Wo2  = (const float*)d_in[10];
    const float* bo2  = (const float*)d_in[11];
    float* out = (float*)d_out;

    k1<<<K1_BLOCKS, 128>>>(x, Wq, bq, Wk, bk, Wv, bv, Wo1, bo1, Wo2, seg);
    attn_kernel<<<dim3(NG, 8), 128>>>();
    final_kernel<<<NG, 256>>>(bo2, out);
}